// round 5
// baseline (speedup 1.0000x reference)
#include <cuda_runtime.h>

#define NN 100000
#define EE 1600000
#define HH 128
#define GG 1000
#define CC 10
#define LL 3
#define BN_EPS 1e-5f

// ---------------- scratch (static device globals; no allocation) ----------------
__device__ float d_g[NN * HH];      // dinv-scaled GEMM output of current layer
__device__ float d_pre[NN * HH];    // pre-BN activations of current layer
__device__ float d_dinv[NN];
__device__ int   d_deg[NN];
__device__ int   d_rowstart[NN];
__device__ int   d_cursor[NN];
__device__ int   d_colsrc[EE];
__device__ float d_bnsum[HH];
__device__ float d_bnsq[HH];
__device__ float d_scale[HH];
__device__ float d_shift[HH];
__device__ float d_pooled[GG * HH];
__device__ int   d_cnt[GG];
__device__ int   d_bsum[128];       // scan block sums (98 used)

// ---------------- graph preprocessing ----------------
__global__ void k_zero_deg() {
    int i = blockIdx.x * 256 + threadIdx.x;
    if (i < NN) d_deg[i] = 0;
}

__global__ void k_count(const int* __restrict__ ei) {
    int e = blockIdx.x * 256 + threadIdx.x;
    if (e >= EE) return;
    atomicAdd(&d_deg[ei[EE + e]], 1);
}

__global__ void k_scan1() {  // 98 blocks x 1024
    __shared__ int sh[1024];
    int i = blockIdx.x * 1024 + threadIdx.x;
    sh[threadIdx.x] = (i < NN) ? d_deg[i] : 0;
    __syncthreads();
    for (int s = 512; s > 0; s >>= 1) {
        if (threadIdx.x < s) sh[threadIdx.x] += sh[threadIdx.x + s];
        __syncthreads();
    }
    if (threadIdx.x == 0) d_bsum[blockIdx.x] = sh[0];
}

__global__ void k_scan2(int nb) {  // 1 thread serial exclusive scan of block sums
    if (threadIdx.x == 0 && blockIdx.x == 0) {
        int acc = 0;
        for (int b = 0; b < nb; b++) { int v = d_bsum[b]; d_bsum[b] = acc; acc += v; }
    }
}

__global__ void k_scan3() {  // 98 blocks x 1024, Hillis-Steele inclusive -> exclusive
    __shared__ int sh[1024];
    int tid = threadIdx.x;
    int i = blockIdx.x * 1024 + tid;
    int v = (i < NN) ? d_deg[i] : 0;
    sh[tid] = v;
    __syncthreads();
    for (int off = 1; off < 1024; off <<= 1) {
        int tv = (tid >= off) ? sh[tid - off] : 0;
        __syncthreads();
        sh[tid] += tv;
        __syncthreads();
    }
    if (i < NN) {
        int excl = sh[tid] - v + d_bsum[blockIdx.x];
        d_rowstart[i] = excl;
        d_cursor[i]   = excl;
    }
}

__global__ void k_fill(const int* __restrict__ ei) {
    int e = blockIdx.x * 256 + threadIdx.x;
    if (e >= EE) return;
    int dd = ei[EE + e];
    int pos = atomicAdd(&d_cursor[dd], 1);
    d_colsrc[pos] = ei[e];
}

__global__ void k_dinv() {
    int i = blockIdx.x * 256 + threadIdx.x;
    if (i < NN) d_dinv[i] = rsqrtf(1.0f + (float)d_deg[i]);
}

// ---------------- GEMM: g = dinv * (bn_relu(A) @ W) ----------------
// layer==0: A = x raw (no affine/relu). layer>0: A = d_pre with d_scale/d_shift + relu.
// Block: 128 rows x 128 cols, 256 threads, 8x8 micro-tile (rows ty+16i, cols tx*8+j).
#define GEMM_SMEM_FLOATS (16384 + 128 * 132 + 256)
#define GEMM_SMEM_BYTES  (GEMM_SMEM_FLOATS * 4)

__global__ __launch_bounds__(256, 1) void k_gemm(const float* __restrict__ x0,
                                                 const float* __restrict__ W,
                                                 int layer) {
    extern __shared__ float sm[];
    float* Ws  = sm;                       // [128][128]
    float* As  = sm + 16384;               // [128][132]
    float* ssc = sm + 16384 + 128 * 132;   // [128]
    float* ssh = ssc + 128;                // [128]

    int t = threadIdx.x;
    const float* A = (layer == 0) ? x0 : d_pre;
    bool aff = (layer != 0);

    if (t < 128) {
        ssc[t] = aff ? d_scale[t] : 1.0f;
        ssh[t] = aff ? d_shift[t] : 0.0f;
    }
    // load W tile (entire 128x128)
#pragma unroll
    for (int i = 0; i < 16; i++) {
        int f = t + i * 256;
        int k = f >> 5;
        int j4 = (f & 31) * 4;
        *(float4*)&Ws[k * 128 + j4] = *(const float4*)&W[k * 128 + j4];
    }
    __syncthreads();  // ssc/ssh visible before A-load transform

    int blockRow = blockIdx.x * 128;
#pragma unroll
    for (int i = 0; i < 16; i++) {
        int f = t + i * 256;
        int r = f >> 5;
        int k4 = (f & 31) * 4;
        int grow = blockRow + r;
        float4 a4 = make_float4(0.f, 0.f, 0.f, 0.f);
        if (grow < NN) a4 = *(const float4*)&A[grow * HH + k4];
        if (aff) {
            a4.x = fmaxf(fmaf(a4.x, ssc[k4 + 0], ssh[k4 + 0]), 0.f);
            a4.y = fmaxf(fmaf(a4.y, ssc[k4 + 1], ssh[k4 + 1]), 0.f);
            a4.z = fmaxf(fmaf(a4.z, ssc[k4 + 2], ssh[k4 + 2]), 0.f);
            a4.w = fmaxf(fmaf(a4.w, ssc[k4 + 3], ssh[k4 + 3]), 0.f);
        }
        *(float4*)&As[r * 132 + k4] = a4;
    }
    __syncthreads();

    int tx = t & 15;
    int ty = t >> 4;
    float acc[8][8];
#pragma unroll
    for (int i = 0; i < 8; i++)
#pragma unroll
        for (int j = 0; j < 8; j++) acc[i][j] = 0.f;

#pragma unroll 8
    for (int k = 0; k < 128; k++) {
        float b[8];
        float4 b0 = *(float4*)&Ws[k * 128 + tx * 8];
        float4 b1v = *(float4*)&Ws[k * 128 + tx * 8 + 4];
        b[0] = b0.x; b[1] = b0.y; b[2] = b0.z; b[3] = b0.w;
        b[4] = b1v.x; b[5] = b1v.y; b[6] = b1v.z; b[7] = b1v.w;
        float a[8];
#pragma unroll
        for (int i = 0; i < 8; i++) a[i] = As[(ty + i * 16) * 132 + k];
#pragma unroll
        for (int i = 0; i < 8; i++)
#pragma unroll
            for (int j = 0; j < 8; j++) acc[i][j] = fmaf(a[i], b[j], acc[i][j]);
    }

#pragma unroll
    for (int i = 0; i < 8; i++) {
        int grow = blockRow + ty + i * 16;
        if (grow < NN) {
            float dv = d_dinv[grow];
            float4 o0, o1;
            o0.x = acc[i][0] * dv; o0.y = acc[i][1] * dv;
            o0.z = acc[i][2] * dv; o0.w = acc[i][3] * dv;
            o1.x = acc[i][4] * dv; o1.y = acc[i][5] * dv;
            o1.z = acc[i][6] * dv; o1.w = acc[i][7] * dv;
            *(float4*)&d_g[grow * HH + tx * 8]     = o0;
            *(float4*)&d_g[grow * HH + tx * 8 + 4] = o1;
        }
    }
}

// ---------------- aggregation + combine + BN stats ----------------
#define AGG_R 32
__global__ void k_zero_bn() {
    int i = threadIdx.x;
    if (i < HH) { d_bnsum[i] = 0.f; d_bnsq[i] = 0.f; }
}

__global__ void k_agg(const float* __restrict__ bias) {
    int j = threadIdx.x;  // 0..127
    int base = blockIdx.x * AGG_R;
    float lsum = 0.f, lsq = 0.f;
    float bj = bias[j];
#pragma unroll 1
    for (int r = 0; r < AGG_R; r++) {
        int d = base + r;
        if (d >= NN) break;
        float acc  = d_g[d * HH + j];  // self-loop term (already dinv-scaled)
        float acc2 = 0.f;
        int s0 = d_rowstart[d];
        int cnt = d_deg[d];
        int e = 0;
        for (; e + 1 < cnt; e += 2) {
            int s1 = d_colsrc[s0 + e];
            int s2 = d_colsrc[s0 + e + 1];
            acc  += d_g[s1 * HH + j];
            acc2 += d_g[s2 * HH + j];
        }
        if (e < cnt) acc += d_g[d_colsrc[s0 + e] * HH + j];
        float v = d_dinv[d] * (acc + acc2) + bj;
        d_pre[d * HH + j] = v;
        lsum += v;
        lsq = fmaf(v, v, lsq);
    }
    atomicAdd(&d_bnsum[j], lsum);
    atomicAdd(&d_bnsq[j], lsq);
}

__global__ void k_bnfin(const float* __restrict__ gamma, const float* __restrict__ beta) {
    int j = threadIdx.x;
    float mean = d_bnsum[j] * (1.0f / NN);
    float var  = d_bnsq[j] * (1.0f / NN) - mean * mean;
    float s = gamma[j] * rsqrtf(var + BN_EPS);
    d_scale[j] = s;
    d_shift[j] = beta[j] - mean * s;
}

// ---------------- global mean pool (batch is sorted) ----------------
#define POOL_R 256
__global__ void k_zero_pool() {
    int i = blockIdx.x * 256 + threadIdx.x;
    if (i < GG * HH) d_pooled[i] = 0.f;
    if (i < GG) d_cnt[i] = 0;
}

__global__ void k_pool(const int* __restrict__ batch) {
    int j = threadIdx.x;  // 0..127
    int base = blockIdx.x * POOL_R;
    if (base >= NN) return;
    int end = base + POOL_R;
    if (end > NN) end = NN;
    int cur = batch[base];
    float acc = 0.f;
    int run = 0;
    float sc = d_scale[j], sh = d_shift[j];
    for (int row = base; row < end; row++) {
        int b = batch[row];
        if (b != cur) {
            atomicAdd(&d_pooled[cur * HH + j], acc);
            if (j == 0) atomicAdd(&d_cnt[cur], run);
            acc = 0.f; run = 0; cur = b;
        }
        float v = d_pre[row * HH + j];
        v = fmaxf(fmaf(v, sc, sh), 0.f);
        acc += v;
        run++;
    }
    atomicAdd(&d_pooled[cur * HH + j], acc);
    if (j == 0) atomicAdd(&d_cnt[cur], run);
}

// ---------------- classifier MLP ----------------
__global__ void k_mlp(const float* __restrict__ w1, const float* __restrict__ b1,
                      const float* __restrict__ w2, const float* __restrict__ b2,
                      float* __restrict__ out) {
    __shared__ float p[128];
    __shared__ float z[64];
    int t = threadIdx.x;  // 0..63
    int g = blockIdx.x;
    float c = fmaxf((float)d_cnt[g], 1.0f);
    float inv = 1.0f / c;
    p[t]      = d_pooled[g * HH + t] * inv;
    p[t + 64] = d_pooled[g * HH + 64 + t] * inv;
    __syncthreads();
    float a = b1[t];
#pragma unroll 8
    for (int k = 0; k < 128; k++) a = fmaf(p[k], w1[k * 64 + t], a);
    z[t] = fmaxf(a, 0.f);
    __syncthreads();
    if (t < CC) {
        float o = b2[t];
#pragma unroll
        for (int q = 0; q < 64; q++) o = fmaf(z[q], w2[q * CC + t], o);
        out[g * CC + t] = o;
    }
}

// ---------------- launch ----------------
extern "C" void kernel_launch(void* const* d_in, const int* in_sizes, int n_in,
                              void* d_out, int out_size) {
    const float* x      = (const float*)d_in[0];
    const float* conv_w = (const float*)d_in[1];
    const float* conv_b = (const float*)d_in[2];
    const float* bng    = (const float*)d_in[3];
    const float* bnb    = (const float*)d_in[4];
    const float* w1     = (const float*)d_in[5];
    const float* b1     = (const float*)d_in[6];
    const float* w2     = (const float*)d_in[7];
    const float* b2     = (const float*)d_in[8];
    const int*   ei     = (const int*)d_in[9];    // int32: JAX x64-disabled
    const int*   batch  = (const int*)d_in[10];   // int32
    float* out = (float*)d_out;

    cudaFuncSetAttribute(k_gemm, cudaFuncAttributeMaxDynamicSharedMemorySize,
                         GEMM_SMEM_BYTES);

    const int NB_SCAN = (NN + 1023) / 1024;  // 98

    // CSR build by dst + degrees (once per call)
    k_zero_deg<<<(NN + 255) / 256, 256>>>();
    k_count<<<(EE + 255) / 256, 256>>>(ei);
    k_scan1<<<NB_SCAN, 1024>>>();
    k_scan2<<<1, 32>>>(NB_SCAN);
    k_scan3<<<NB_SCAN, 1024>>>();
    k_fill<<<(EE + 255) / 256, 256>>>(ei);
    k_dinv<<<(NN + 255) / 256, 256>>>();

    const int GEMM_GRID = (NN + 127) / 128;  // 782
    for (int l = 0; l < LL; l++) {
        k_gemm<<<GEMM_GRID, 256, GEMM_SMEM_BYTES>>>(x, conv_w + l * HH * HH, l);
        k_zero_bn<<<1, 128>>>();
        k_agg<<<(NN + AGG_R - 1) / AGG_R, 128>>>(conv_b + l * HH);
        k_bnfin<<<1, 128>>>(bng + l * HH, bnb + l * HH);
    }

    k_zero_pool<<<(GG * HH + 255) / 256, 256>>>();
    k_pool<<<(NN + POOL_R - 1) / POOL_R, 128>>>(batch);
    k_mlp<<<GG, 64>>>(w1, b1, w2, b2, out);
}